// round 8
// baseline (speedup 1.0000x reference)
#include <cuda_runtime.h>
#include <cuda_fp16.h>

namespace {

constexpr int kNodes = 50000;
constexpr int kEdges = 800000;
constexpr int kScanBlocks = (kNodes + 255) / 256;  // 196

// Scratch (allocation-free __device__ globals).
__device__ float4 g_xc  [kNodes * 32];  // fp32 normalized caps (capsule-major: idx = n*32 + c*4 + k)
__device__ uint4  g_xch4[kNodes * 16];  // fp16 caps, j-interleaved: idx = n*16 + j*8 + c (j = dim-half)
__device__ float4 g_u   [kNodes * 32];  // routing state, same layout as g_xc
__device__ int    g_count [kNodes + 1];
__device__ int    g_incl  [kNodes + 1];
__device__ int    g_bsum  [kScanBlocks];
__device__ int    g_bpre  [kScanBlocks];
__device__ int    g_offs  [kNodes + 1];  // CSR row offsets (by target)
__device__ int    g_cursor[kNodes];
__device__ int    g_srcs  [kEdges];      // CSR column (source node per edge)
__device__ int    g_is_i32;              // edge_index dtype flag

__device__ __forceinline__ float group4_sum(float v) {
    v += __shfl_xor_sync(0xffffffffu, v, 1);
    v += __shfl_xor_sync(0xffffffffu, v, 2);
    return v;
}

__device__ __forceinline__ int load_idx(const void* ei, long long off) {
    if (g_is_i32) return ((const int*)ei)[off];
    return (int)((const long long*)ei)[off];
}

// ---- preprocessing: dtype detect + counting sort of edges by target ----

__global__ void detect_kernel(const unsigned int* __restrict__ w) {
    unsigned int acc = 0;
    for (int i = threadIdx.x; i < 1024; i += 32) acc |= w[2 * i + 1];
    #pragma unroll
    for (int d = 1; d < 32; d <<= 1) acc |= __shfl_xor_sync(0xffffffffu, acc, d);
    if (threadIdx.x == 0) g_is_i32 = (acc != 0) ? 1 : 0;
}

__global__ void zero_count_kernel() {
    int i = blockIdx.x * blockDim.x + threadIdx.x;
    if (i <= kNodes) g_count[i] = 0;
}

__global__ void hist_kernel(const void* __restrict__ ei) {
    int e = blockIdx.x * blockDim.x + threadIdx.x;
    if (e >= kEdges) return;
    atomicAdd(&g_count[load_idx(ei, (long long)kEdges + e)], 1);
}

// S1: per-block inclusive scan of counts (256/block) + block totals.
__global__ void __launch_bounds__(256) scan1_kernel() {
    __shared__ int warp_tot[8];
    int i    = blockIdx.x * 256 + threadIdx.x;
    int lane = threadIdx.x & 31;
    int wid  = threadIdx.x >> 5;

    int v = (i < kNodes) ? g_count[i] : 0;
    int x = v;
    #pragma unroll
    for (int d = 1; d < 32; d <<= 1) {
        int y = __shfl_up_sync(0xffffffffu, x, d);
        if (lane >= d) x += y;
    }
    if (lane == 31) warp_tot[wid] = x;
    __syncthreads();
    if (wid == 0) {
        int t = (lane < 8) ? warp_tot[lane] : 0;
        #pragma unroll
        for (int d = 1; d < 8; d <<= 1) {
            int y = __shfl_up_sync(0xffffffffu, t, d);
            if (lane >= d) t += y;
        }
        if (lane < 8) warp_tot[lane] = t;
    }
    __syncthreads();
    int incl = x + (wid > 0 ? warp_tot[wid - 1] : 0);
    if (i < kNodes) g_incl[i] = incl;
    if (threadIdx.x == 255) g_bsum[blockIdx.x] = incl;
}

// S2: exclusive scan of 196 block totals (single tiny block).
__global__ void __launch_bounds__(256) scan2_kernel() {
    __shared__ int warp_tot[8];
    int lane = threadIdx.x & 31;
    int wid  = threadIdx.x >> 5;
    int v = (threadIdx.x < kScanBlocks) ? g_bsum[threadIdx.x] : 0;
    int x = v;
    #pragma unroll
    for (int d = 1; d < 32; d <<= 1) {
        int y = __shfl_up_sync(0xffffffffu, x, d);
        if (lane >= d) x += y;
    }
    if (lane == 31) warp_tot[wid] = x;
    __syncthreads();
    if (wid == 0) {
        int t = (lane < 8) ? warp_tot[lane] : 0;
        #pragma unroll
        for (int d = 1; d < 8; d <<= 1) {
            int y = __shfl_up_sync(0xffffffffu, t, d);
            if (lane >= d) t += y;
        }
        if (lane < 8) warp_tot[lane] = t;
    }
    __syncthreads();
    int incl = x + (wid > 0 ? warp_tot[wid - 1] : 0);
    if (threadIdx.x < kScanBlocks) g_bpre[threadIdx.x] = incl - v;  // exclusive
}

// S3: offs[i] = bpre[blk] + incl[i] - count[i]; cursor = offs; offs[N] = E.
__global__ void __launch_bounds__(256) scan3_kernel() {
    int i = blockIdx.x * 256 + threadIdx.x;
    if (i < kNodes) {
        int off = g_bpre[blockIdx.x] + g_incl[i] - g_count[i];
        g_offs[i]   = off;
        g_cursor[i] = off;
    }
    if (i == 0) g_offs[kNodes] = kEdges;
}

__global__ void scatter_kernel(const void* __restrict__ ei) {
    int e = blockIdx.x * blockDim.x + threadIdx.x;
    if (e >= kEdges) return;
    int s = load_idx(ei, e);
    int g = load_idx(ei, (long long)kEdges + e);
    int pos = atomicAdd(&g_cursor[g], 1);
    g_srcs[pos] = s;
}

// ---- compute ----

// xc = l2norm_per_capsule(x); write fp32 + j-interleaved fp16 copy.
// One warp per node; lane t owns float4 #t (dims [4t, 4t+4)).
__global__ void __launch_bounds__(256) init_kernel(const float* __restrict__ x) {
    int gid  = blockIdx.x * blockDim.x + threadIdx.x;
    int node = gid >> 5;
    if (node >= kNodes) return;
    int t   = gid & 31;
    int idx = node * 32 + t;

    float4 v = reinterpret_cast<const float4*>(x)[idx];
    float ss = group4_sum(v.x * v.x + v.y * v.y + v.z * v.z + v.w * v.w);
    float s  = 1.0f / fmaxf(sqrtf(ss), 1e-12f);
    v.x *= s; v.y *= s; v.z *= s; v.w *= s;
    g_xc[idx] = v;

    // fp16 copy. Lane t's dims belong to capsule c = t>>2, half j = (t>>1)&1,
    // 8-byte slot h = t&1 within the 16B capsule-chunk g_xch4[n*16 + j*8 + c].
    half2 a = __floats2half2_rn(v.x, v.y);
    half2 b = __floats2half2_rn(v.z, v.w);
    uint2 w;
    w.x = *reinterpret_cast<const unsigned int*>(&a);
    w.y = *reinterpret_cast<const unsigned int*>(&b);
    int c = t >> 2, j = (t >> 1) & 1, h = t & 1;
    reinterpret_cast<uint2*>(g_xch4 + node * 16 + j * 8 + c)[h] = w;
}

// One routing iteration, capsule-per-lane: warp n owns target node n.
// Lane = (esub, cap) = (lane>>3, lane&7): 4 edges per warp-step, 8 lanes/edge.
// Dot is lane-local; softmax = 3 shfls per 4 edges; msg accumulates in regs;
// one butterfly merge at the tail. No max-subtract (caps unit => p in [-1,1]).
template <bool FIRST, bool WRITE_OUT>
__global__ void __launch_bounds__(256) route_kernel(float* __restrict__ out) {
    int gid  = blockIdx.x * blockDim.x + threadIdx.x;
    int node = gid >> 5;
    if (node >= kNodes) return;
    int lane = threadIdx.x & 31;
    int cap  = lane & 7;
    int esub = lane >> 3;

    // u capsule `cap` of this node, lane-local (broadcast across esub groups).
    float u_[16];
    {
        const float4* ub = (FIRST ? g_xc : g_u) + node * 32 + cap * 4;
        #pragma unroll
        for (int k = 0; k < 4; ++k) {
            float4 t4 = ub[k];
            u_[4 * k]     = t4.x;
            u_[4 * k + 1] = t4.y;
            u_[4 * k + 2] = t4.z;
            u_[4 * k + 3] = t4.w;
        }
    }

    int beg = g_offs[node];
    int end = g_offs[node + 1];

    float acc[16];
    #pragma unroll
    for (int d = 0; d < 16; ++d) acc[d] = 0.f;

    for (int i = beg; i < end; i += 4) {
        int  ei    = i + esub;
        bool valid = ei < end;
        int  s     = g_srcs[valid ? ei : end - 1];

        const uint4* zb = g_xch4 + s * 16 + cap;
        uint4 a = zb[0];   // capsule dims 0..7  (fp16)
        uint4 b = zb[8];   // capsule dims 8..15 (fp16)

        float zf[16];
        {
            float2 f;
            f = __half22float2(*reinterpret_cast<const half2*>(&a.x)); zf[0]=f.x;  zf[1]=f.y;
            f = __half22float2(*reinterpret_cast<const half2*>(&a.y)); zf[2]=f.x;  zf[3]=f.y;
            f = __half22float2(*reinterpret_cast<const half2*>(&a.z)); zf[4]=f.x;  zf[5]=f.y;
            f = __half22float2(*reinterpret_cast<const half2*>(&a.w)); zf[6]=f.x;  zf[7]=f.y;
            f = __half22float2(*reinterpret_cast<const half2*>(&b.x)); zf[8]=f.x;  zf[9]=f.y;
            f = __half22float2(*reinterpret_cast<const half2*>(&b.y)); zf[10]=f.x; zf[11]=f.y;
            f = __half22float2(*reinterpret_cast<const half2*>(&b.z)); zf[12]=f.x; zf[13]=f.y;
            f = __half22float2(*reinterpret_cast<const half2*>(&b.w)); zf[14]=f.x; zf[15]=f.y;
        }

        float p = 0.f;
        #pragma unroll
        for (int d = 0; d < 16; ++d) p += zf[d] * u_[d];

        float e0 = __expf(p);
        float q  = e0;
        q += __shfl_xor_sync(0xffffffffu, q, 1);
        q += __shfl_xor_sync(0xffffffffu, q, 2);
        q += __shfl_xor_sync(0xffffffffu, q, 4);
        float w = valid ? __fdividef(e0, q) : 0.f;

        #pragma unroll
        for (int d = 0; d < 16; ++d) acc[d] += zf[d] * w;
    }

    // Merge the 4 edge-groups (lanes c, c+8, c+16, c+24 hold partials of cap c).
    #pragma unroll
    for (int d = 0; d < 16; ++d) {
        acc[d] += __shfl_xor_sync(0xffffffffu, acc[d], 8);
        acc[d] += __shfl_xor_sync(0xffffffffu, acc[d], 16);
    }

    // u_new = l2norm_per_capsule(acc + xc) — lane-local, no shuffles.
    const float4* cb = g_xc + node * 32 + cap * 4;
    float v[16];
    float ss = 0.f;
    #pragma unroll
    for (int k = 0; k < 4; ++k) {
        float4 c4 = cb[k];
        v[4 * k]     = acc[4 * k]     + c4.x;
        v[4 * k + 1] = acc[4 * k + 1] + c4.y;
        v[4 * k + 2] = acc[4 * k + 2] + c4.z;
        v[4 * k + 3] = acc[4 * k + 3] + c4.w;
        ss += v[4*k]*v[4*k] + v[4*k+1]*v[4*k+1] + v[4*k+2]*v[4*k+2] + v[4*k+3]*v[4*k+3];
    }
    float sc = 1.0f / fmaxf(sqrtf(ss), 1e-12f);

    if (esub == 0) {  // one writer group; all groups hold identical results
        float4* dst = (WRITE_OUT ? reinterpret_cast<float4*>(out) : g_u) + node * 32 + cap * 4;
        #pragma unroll
        for (int k = 0; k < 4; ++k)
            dst[k] = make_float4(v[4*k] * sc, v[4*k+1] * sc, v[4*k+2] * sc, v[4*k+3] * sc);
    }
}

}  // namespace

extern "C" void kernel_launch(void* const* d_in, const int* in_sizes, int n_in,
                              void* d_out, int out_size) {
    const float* x  = (const float*)d_in[0];
    const void*  ei = d_in[1];   // [2, E], int32 or int64 (detected on-device)
    float* out = (float*)d_out;

    const int nodeBlocks = (kNodes * 32 + 255) / 256;
    const int edgeBlocks = (kEdges + 255) / 256;

    detect_kernel<<<1, 32>>>((const unsigned int*)ei);
    zero_count_kernel<<<(kNodes + 256) / 256, 256>>>();
    hist_kernel<<<edgeBlocks, 256>>>(ei);
    scan1_kernel<<<kScanBlocks, 256>>>();
    scan2_kernel<<<1, 256>>>();
    scan3_kernel<<<kScanBlocks, 256>>>();
    scatter_kernel<<<edgeBlocks, 256>>>(ei);
    init_kernel<<<nodeBlocks, 256>>>(x);

    route_kernel<true,  false><<<nodeBlocks, 256>>>(nullptr);
    route_kernel<false, false><<<nodeBlocks, 256>>>(nullptr);
    route_kernel<false, true ><<<nodeBlocks, 256>>>(out);
}

// round 10
// speedup vs baseline: 1.0785x; 1.0785x over previous
#include <cuda_runtime.h>
#include <cuda_fp16.h>

namespace {

constexpr int kNodes = 50000;
constexpr int kEdges = 800000;
constexpr int kScanBlocks = (kNodes + 255) / 256;  // 196

// Scratch (allocation-free __device__ globals; 16B-aligned types where needed).
__device__ float4 g_xc [kNodes * 32];  // fp32 normalized caps (residual + norm path)
__device__ uint2  g_xch[kNodes * 32];  // fp16 copy: lane t's 4 dims as 2x half2
__device__ float4 g_u  [kNodes * 32];  // routing state (updated in place per node)
__device__ int    g_count [kNodes + 1];
__device__ int    g_incl  [kNodes + 1];
__device__ int    g_bsum  [kScanBlocks];
__device__ int    g_bpre  [kScanBlocks];
__device__ int    g_offs  [kNodes + 1];  // CSR row offsets (by target)
__device__ int    g_cursor[kNodes];
__device__ int    g_srcs  [kEdges];      // CSR column (source node per edge)
__device__ int    g_is_i32;              // edge_index dtype flag

__device__ __forceinline__ float group4_sum(float v) {
    v += __shfl_xor_sync(0xffffffffu, v, 1);
    v += __shfl_xor_sync(0xffffffffu, v, 2);
    return v;
}

__device__ __forceinline__ float cap_sum(float v) {
    v += __shfl_xor_sync(0xffffffffu, v, 4);
    v += __shfl_xor_sync(0xffffffffu, v, 8);
    v += __shfl_xor_sync(0xffffffffu, v, 16);
    return v;
}

__device__ __forceinline__ int load_idx(const void* ei, long long off) {
    if (g_is_i32) return ((const int*)ei)[off];
    return (int)((const long long*)ei)[off];
}

__device__ __forceinline__ float4 load_z_h(int idx) {
    uint2 w = g_xch[idx];
    float2 a = __half22float2(*reinterpret_cast<const half2*>(&w.x));
    float2 b = __half22float2(*reinterpret_cast<const half2*>(&w.y));
    return make_float4(a.x, a.y, b.x, b.y);
}

// ---- preprocessing: dtype detect + counting sort of edges by target ----

__global__ void detect_kernel(const unsigned int* __restrict__ w) {
    unsigned int acc = 0;
    for (int i = threadIdx.x; i < 1024; i += 32) acc |= w[2 * i + 1];
    #pragma unroll
    for (int d = 1; d < 32; d <<= 1) acc |= __shfl_xor_sync(0xffffffffu, acc, d);
    if (threadIdx.x == 0) g_is_i32 = (acc != 0) ? 1 : 0;
}

__global__ void zero_count_kernel() {
    int i = blockIdx.x * blockDim.x + threadIdx.x;
    if (i <= kNodes) g_count[i] = 0;
}

__global__ void hist_kernel(const void* __restrict__ ei) {
    int e = blockIdx.x * blockDim.x + threadIdx.x;
    if (e >= kEdges) return;
    atomicAdd(&g_count[load_idx(ei, (long long)kEdges + e)], 1);
}

// S1: per-block inclusive scan of counts (256/block) + block totals.
__global__ void __launch_bounds__(256) scan1_kernel() {
    __shared__ int warp_tot[8];
    int i    = blockIdx.x * 256 + threadIdx.x;
    int lane = threadIdx.x & 31;
    int wid  = threadIdx.x >> 5;

    int v = (i < kNodes) ? g_count[i] : 0;
    int x = v;
    #pragma unroll
    for (int d = 1; d < 32; d <<= 1) {
        int y = __shfl_up_sync(0xffffffffu, x, d);
        if (lane >= d) x += y;
    }
    if (lane == 31) warp_tot[wid] = x;
    __syncthreads();
    if (wid == 0) {
        int t = (lane < 8) ? warp_tot[lane] : 0;
        #pragma unroll
        for (int d = 1; d < 8; d <<= 1) {
            int y = __shfl_up_sync(0xffffffffu, t, d);
            if (lane >= d) t += y;
        }
        if (lane < 8) warp_tot[lane] = t;
    }
    __syncthreads();
    int incl = x + (wid > 0 ? warp_tot[wid - 1] : 0);
    if (i < kNodes) g_incl[i] = incl;
    if (threadIdx.x == 255) g_bsum[blockIdx.x] = incl;
}

// S2: exclusive scan of 196 block totals (single tiny block).
__global__ void __launch_bounds__(256) scan2_kernel() {
    __shared__ int warp_tot[8];
    int lane = threadIdx.x & 31;
    int wid  = threadIdx.x >> 5;
    int v = (threadIdx.x < kScanBlocks) ? g_bsum[threadIdx.x] : 0;
    int x = v;
    #pragma unroll
    for (int d = 1; d < 32; d <<= 1) {
        int y = __shfl_up_sync(0xffffffffu, x, d);
        if (lane >= d) x += y;
    }
    if (lane == 31) warp_tot[wid] = x;
    __syncthreads();
    if (wid == 0) {
        int t = (lane < 8) ? warp_tot[lane] : 0;
        #pragma unroll
        for (int d = 1; d < 8; d <<= 1) {
            int y = __shfl_up_sync(0xffffffffu, t, d);
            if (lane >= d) t += y;
        }
        if (lane < 8) warp_tot[lane] = t;
    }
    __syncthreads();
    int incl = x + (wid > 0 ? warp_tot[wid - 1] : 0);
    if (threadIdx.x < kScanBlocks) g_bpre[threadIdx.x] = incl - v;  // exclusive
}

// S3: offs[i] = bpre[blk] + incl[i] - count[i]; cursor = offs; offs[N] = E.
__global__ void __launch_bounds__(256) scan3_kernel() {
    int i = blockIdx.x * 256 + threadIdx.x;
    if (i < kNodes) {
        int off = g_bpre[blockIdx.x] + g_incl[i] - g_count[i];
        g_offs[i]   = off;
        g_cursor[i] = off;
    }
    if (i == 0) g_offs[kNodes] = kEdges;
}

__global__ void scatter_kernel(const void* __restrict__ ei) {
    int e = blockIdx.x * blockDim.x + threadIdx.x;
    if (e >= kEdges) return;
    int s = load_idx(ei, e);
    int g = load_idx(ei, (long long)kEdges + e);
    int pos = atomicAdd(&g_cursor[g], 1);
    g_srcs[pos] = s;
}

// ---- compute ----

// xc = l2norm_per_capsule(x); write fp32 + fp16 copies. One warp per node.
__global__ void __launch_bounds__(256) init_kernel(const float* __restrict__ x) {
    int gid  = blockIdx.x * blockDim.x + threadIdx.x;
    int node = gid >> 5;
    if (node >= kNodes) return;
    int t   = gid & 31;
    int idx = node * 32 + t;

    float4 v = reinterpret_cast<const float4*>(x)[idx];
    float ss = group4_sum(v.x * v.x + v.y * v.y + v.z * v.z + v.w * v.w);
    float s  = 1.0f / fmaxf(sqrtf(ss), 1e-12f);
    v.x *= s; v.y *= s; v.z *= s; v.w *= s;
    g_xc[idx] = v;

    half2 a = __floats2half2_rn(v.x, v.y);
    half2 b = __floats2half2_rn(v.z, v.w);
    uint2 w;
    w.x = *reinterpret_cast<const unsigned int*>(&a);
    w.y = *reinterpret_cast<const unsigned int*>(&b);
    g_xch[idx] = w;
}

// One full routing iteration fused per node: warp n owns target node n.
// Lane t holds dims [4t,4t+4); capsule of lane t = t>>2.
// 4 independent edges in flight per loop iteration (ILP for shfl/exp chains).
// Softmax needs no max-subtract: capsules are unit vectors => p in [-1,1].
template <bool FIRST, bool WRITE_OUT>
__global__ void __launch_bounds__(256) route_kernel(float* __restrict__ out) {
    int gid  = blockIdx.x * blockDim.x + threadIdx.x;
    int node = gid >> 5;
    if (node >= kNodes) return;
    int t   = gid & 31;
    int idx = node * 32 + t;

    float4 c = g_xc[idx];
    float4 u = FIRST ? c : g_u[idx];

    int beg = g_offs[node];
    int end = g_offs[node + 1];

    float4 acc = make_float4(0.f, 0.f, 0.f, 0.f);
    int i = beg;
    for (; i + 4 <= end; i += 4) {
        int s0 = g_srcs[i];
        int s1 = g_srcs[i + 1];
        int s2 = g_srcs[i + 2];
        int s3 = g_srcs[i + 3];
        float4 z0 = load_z_h(s0 * 32 + t);
        float4 z1 = load_z_h(s1 * 32 + t);
        float4 z2 = load_z_h(s2 * 32 + t);
        float4 z3 = load_z_h(s3 * 32 + t);

        float p0 = group4_sum(z0.x * u.x + z0.y * u.y + z0.z * u.z + z0.w * u.w);
        float p1 = group4_sum(z1.x * u.x + z1.y * u.y + z1.z * u.z + z1.w * u.w);
        float p2 = group4_sum(z2.x * u.x + z2.y * u.y + z2.z * u.z + z2.w * u.w);
        float p3 = group4_sum(z3.x * u.x + z3.y * u.y + z3.z * u.z + z3.w * u.w);

        float e0 = __expf(p0), e1 = __expf(p1), e2 = __expf(p2), e3 = __expf(p3);
        float w0 = __fdividef(e0, cap_sum(e0));
        float w1 = __fdividef(e1, cap_sum(e1));
        float w2 = __fdividef(e2, cap_sum(e2));
        float w3 = __fdividef(e3, cap_sum(e3));

        acc.x += z0.x * w0 + z1.x * w1 + z2.x * w2 + z3.x * w3;
        acc.y += z0.y * w0 + z1.y * w1 + z2.y * w2 + z3.y * w3;
        acc.z += z0.z * w0 + z1.z * w1 + z2.z * w2 + z3.z * w3;
        acc.w += z0.w * w0 + z1.w * w1 + z2.w * w2 + z3.w * w3;
    }
    for (; i < end; ++i) {
        int s0 = g_srcs[i];
        float4 z0 = load_z_h(s0 * 32 + t);
        float p0 = group4_sum(z0.x * u.x + z0.y * u.y + z0.z * u.z + z0.w * u.w);
        float e0 = __expf(p0);
        float w0 = __fdividef(e0, cap_sum(e0));
        acc.x += z0.x * w0;
        acc.y += z0.y * w0;
        acc.z += z0.z * w0;
        acc.w += z0.w * w0;
    }

    // u_new = l2norm_per_capsule(acc + xc); only this warp touches row `node`.
    float4 v = make_float4(acc.x + c.x, acc.y + c.y, acc.z + c.z, acc.w + c.w);
    float ss = group4_sum(v.x * v.x + v.y * v.y + v.z * v.z + v.w * v.w);
    float s  = 1.0f / fmaxf(sqrtf(ss), 1e-12f);
    v.x *= s; v.y *= s; v.z *= s; v.w *= s;

    if (WRITE_OUT) {
        reinterpret_cast<float4*>(out)[idx] = v;
    } else {
        g_u[idx] = v;
    }
}

}  // namespace

extern "C" void kernel_launch(void* const* d_in, const int* in_sizes, int n_in,
                              void* d_out, int out_size) {
    const float* x  = (const float*)d_in[0];
    const void*  ei = d_in[1];   // [2, E], int32 or int64 (detected on-device)
    float* out = (float*)d_out;

    const int nodeBlocks = (kNodes * 32 + 255) / 256;
    const int edgeBlocks = (kEdges + 255) / 256;

    detect_kernel<<<1, 32>>>((const unsigned int*)ei);
    zero_count_kernel<<<(kNodes + 256) / 256, 256>>>();
    hist_kernel<<<edgeBlocks, 256>>>(ei);
    scan1_kernel<<<kScanBlocks, 256>>>();
    scan2_kernel<<<1, 256>>>();
    scan3_kernel<<<kScanBlocks, 256>>>();
    scatter_kernel<<<edgeBlocks, 256>>>(ei);
    init_kernel<<<nodeBlocks, 256>>>(x);

    route_kernel<true,  false><<<nodeBlocks, 256>>>(nullptr);
    route_kernel<false, false><<<nodeBlocks, 256>>>(nullptr);
    route_kernel<false, true ><<<nodeBlocks, 256>>>(out);
}